// round 7
// baseline (speedup 1.0000x reference)
#include <cuda_runtime.h>
#include <cstdint>

#define Nn   8192
#define Ee   262144
#define Tt   2048
#define NMAT 128          // matvec blocks (64 rows / 64 cols each)
#define NBLK (NMAT + 1)   // + 1 LSTM block
#define NTHR 512

// ---- scratch (device globals; no allocation allowed) ----
__device__ float g_v[Nn];        // xTB - x
__device__ float g_x1[Nn];       // edge scatter result
__device__ float g_x2[Nn];       // W3@(W2@v+b2)+b3 (seeded with b3, atomic-accumulated)
__device__ int   g_done;         // matvec blocks finished

// dynamic smem:
//   matvec blocks: s_v[8192] + s_x21[64]                    (~33 KB)
//   LSTM block   : s_cur[2048] + s_h[8+16384] + red[17]     (~74 KB)
#define SMEM_BYTES ((2048 + 8 + 16384 + 17) * 4)

__device__ __forceinline__ float tanhap(float x) {
    float y;
    asm("tanh.approx.f32 %0, %1;" : "=f"(y) : "f"(x));
    return y;
}

// ---------------------------------------------------------------------------
// K0: init — g_x1 = 0, g_x2 = b3 (atomic accumulation base), v = xTB - x
// ---------------------------------------------------------------------------
__global__ void gl_init(const float* __restrict__ x, const float* __restrict__ xTB,
                        const float* __restrict__ b3) {
    int i = blockIdx.x * blockDim.x + threadIdx.x;
    if (i < Nn) {
        g_v[i]  = xTB[i] - x[i];
        g_x1[i] = 0.f;
        g_x2[i] = b3[i];
    }
    if (i == 0) g_done = 0;
}

// ---------------------------------------------------------------------------
// K1: mega kernel.
//   blocks 0..127 : edge scatter; mv1 rows [64b,64b+64) -> smem x21 chunk;
//                   mv2 column-slice W3[:,64b:64b+64) @ x21chunk -> atomicAdd.
//                   NO inter-block barrier anywhere.
//   block  128    : LSTM (warp 0), W1 dot, wait g_done, final combine.
// ---------------------------------------------------------------------------
__global__ void __launch_bounds__(NTHR, 1)
gl_main(const float* __restrict__ x,   const float* __restrict__ cur,
        const int*   __restrict__ ei,  const float* __restrict__ att,
        const float* __restrict__ W2,  const float* __restrict__ b2,
        const float* __restrict__ W3,
        const float* __restrict__ Wih, const float* __restrict__ Whh,
        const float* __restrict__ bih, const float* __restrict__ bhh,
        const float* __restrict__ W1,  const float* __restrict__ b1,
        const float* __restrict__ x30, float* __restrict__ out) {
    extern __shared__ float smem[];
    const int lane = threadIdx.x & 31;
    const int warp = threadIdx.x >> 5;

    if (blockIdx.x < NMAT) {
        // ================= matvec / scatter block =================
        float4* sv    = (float4*)smem;          // v staged: 8192 floats
        float*  s_x21 = smem + Nn;              // this block's 64 x21 values

        {   // stage v into smem
            const float4* gv = (const float4*)g_v;
            for (int i = threadIdx.x; i < Nn / 4; i += NTHR) sv[i] = gv[i];
        }
        {   // edge scatter
            int tid  = blockIdx.x * NTHR + threadIdx.x;
            int nthr = NMAT * NTHR;
            for (int e = tid; e < Ee; e += nthr) {
                int s = ei[e];
                int d = ei[Ee + e];
                float m = (__ldg(x + s) - __ldg(x + d)) * __ldg(att + e);
                atomicAdd(&g_x1[d], m);
            }
        }
        __syncthreads();

        // ---- mv1: rows [64b, 64b+64), warp-per-row, 16-deep batched loads ----
        const int row0 = blockIdx.x * 64;
        for (int r = warp; r < 64; r += NTHR / 32) {
            int row = row0 + r;
            const float4* wr = (const float4*)(W2 + (size_t)row * Nn) + lane;
            float acc0 = 0.f, acc1 = 0.f;
            #pragma unroll 1
            for (int c = 0; c < 4; ++c) {
                float4 w[16];
                #pragma unroll
                for (int k = 0; k < 16; ++k)
                    w[k] = __ldg(wr + (c * 16 + k) * 32);
                #pragma unroll
                for (int k = 0; k < 16; ++k) {
                    float4 u = sv[lane + (c * 16 + k) * 32];
                    acc0 = fmaf(w[k].x, u.x, acc0);
                    acc1 = fmaf(w[k].y, u.y, acc1);
                    acc0 = fmaf(w[k].z, u.z, acc0);
                    acc1 = fmaf(w[k].w, u.w, acc1);
                }
            }
            float acc = acc0 + acc1;
            #pragma unroll
            for (int o = 16; o; o >>= 1) acc += __shfl_down_sync(0xffffffffu, acc, o);
            if (lane == 0) s_x21[r] = acc + b2[row];
        }
        __syncthreads();

        // ---- mv2: column slice W3[:, 64b:64b+64) @ s_x21, row-per-lane ----
        const float4* sx = (const float4*)s_x21;   // 16 float4 (broadcast reads)
        const int c4 = blockIdx.x * 16;             // float4 column offset
        #pragma unroll 1
        for (int p = 0; p < Nn / NTHR; ++p) {
            int row = p * NTHR + threadIdx.x;        // 512 rows per pass, lane-consecutive
            const float4* wr = (const float4*)(W3 + (size_t)row * Nn) + c4;
            float a0 = 0.f, a1 = 0.f;
            #pragma unroll
            for (int k = 0; k < 16; ++k) {
                float4 w = __ldg(wr + k);
                float4 u = sx[k];
                a0 = fmaf(w.x, u.x, a0);
                a1 = fmaf(w.y, u.y, a1);
                a0 = fmaf(w.z, u.z, a0);
                a1 = fmaf(w.w, u.w, a1);
            }
            atomicAdd(&g_x2[row], a0 + a1);
        }

        __syncthreads();
        if (threadIdx.x == 0) {
            __threadfence();
            atomicAdd(&g_done, 1);
        }
    } else {
        // ================= LSTM block =================
        float* s_cur = smem;                        // [2048]
        float* s_h   = smem + 2048;                 // [8 + 16384]: slot t holds h(t-1)
        float* s_red = smem + 2048 + 8 + 16384;     // [16]
        float* s_x3  = s_red + 16;

        for (int i = threadIdx.x; i < Tt; i += NTHR) s_cur[i] = cur[i];
        if (threadIdx.x < 8) s_h[threadIdx.x] = 0.f;   // h(-1) = 0
        __syncthreads();

        if (warp == 0) {
            // gate-per-lane: lane = gt*8 + u
            // sigmoid gates (gt 0,1,3) via 0.5*tanh(z/2)+0.5; gate 2 tanh
            const int u  = lane & 7;
            const int gt = lane >> 3;
            const bool sig = (gt != 2);
            const float wscale = sig ? 0.5f : 1.0f;
            const float sca = sig ? 0.5f : 1.0f;
            const float scb = sig ? 0.5f : 0.0f;

            float w0 = wscale * Whh[lane * 8 + 0];
            float w1 = wscale * Whh[lane * 8 + 1];
            float w2 = wscale * Whh[lane * 8 + 2];
            float w3 = wscale * Whh[lane * 8 + 3];
            float w4 = wscale * Whh[lane * 8 + 4];
            float w5 = wscale * Whh[lane * 8 + 5];
            float w6 = wscale * Whh[lane * 8 + 6];
            float w7 = wscale * Whh[lane * 8 + 7];
            float a  = wscale * Wih[lane];
            float bb = wscale * (bih[lane] + bhh[lane]);

            float c = 0.f;
            uint32_t hrd = (uint32_t)__cvta_generic_to_shared(s_h);          // h(t-1) at +t*32B
            uint32_t hwr = (uint32_t)__cvta_generic_to_shared(s_h + 8 + u);  // h(t) at +t*32B

            #pragma unroll 4
            for (int t = 0; t < Tt; t++) {
                float xt = s_cur[t];
                float4 hlo, hhi;
                asm volatile("ld.shared.v4.f32 {%0,%1,%2,%3}, [%4];"
                             : "=f"(hlo.x), "=f"(hlo.y), "=f"(hlo.z), "=f"(hlo.w)
                             : "r"(hrd + t * 32));
                asm volatile("ld.shared.v4.f32 {%0,%1,%2,%3}, [%4];"
                             : "=f"(hhi.x), "=f"(hhi.y), "=f"(hhi.z), "=f"(hhi.w)
                             : "r"(hrd + t * 32 + 16));

                float pre  = fmaf(a, xt, bb);
                float acc0 = fmaf(w0, hlo.x, pre);
                float acc1 = w1 * hlo.y;
                acc0 = fmaf(w2, hlo.z, acc0);
                acc1 = fmaf(w3, hlo.w, acc1);
                acc0 = fmaf(w4, hhi.x, acc0);
                acc1 = fmaf(w5, hhi.y, acc1);
                acc0 = fmaf(w6, hhi.z, acc0);
                acc1 = fmaf(w7, hhi.w, acc1);
                float z = acc0 + acc1;

                float v = fmaf(tanhap(z), sca, scb);

                float si = __shfl_sync(0xffffffffu, v, u);
                float sf = __shfl_sync(0xffffffffu, v, 8 + u);
                float tg = __shfl_sync(0xffffffffu, v, 16 + u);
                float so = __shfl_sync(0xffffffffu, v, 24 + u);

                c = fmaf(sf, c, si * tg);
                float h = so * tanhap(c);

                asm volatile("{ .reg .pred p; setp.lt.s32 p, %0, 8;"
                             "  @p st.shared.f32 [%1], %2; }"
                             :: "r"(lane), "r"(hwr + t * 32), "f"(h));
            }
        }
        __syncthreads();   // s_h visible block-wide

        // x3 scalar = W1 · hs_flat + b1
        const float* hist = s_h + 8;
        float part = 0.f;
        for (int k = threadIdx.x; k < Tt * 8; k += NTHR)
            part = fmaf(__ldg(W1 + k), hist[k], part);
        #pragma unroll
        for (int o = 16; o; o >>= 1) part += __shfl_down_sync(0xffffffffu, part, o);
        if (lane == 0) s_red[warp] = part;
        __syncthreads();
        if (threadIdx.x == 0) {
            float s = 0.f;
            #pragma unroll
            for (int w = 0; w < NTHR / 32; w++) s += s_red[w];
            *s_x3 = s + b1[0];
            while (atomicAdd(&g_done, 0) < NMAT) {}  // wait for matvec blocks
            __threadfence();
        }
        __syncthreads();

        float x3 = *s_x3;
        for (int i = threadIdx.x; i < Nn; i += NTHR)
            out[i] = x[i] + g_x1[i] + g_x2[i] + x3 * x30[i];
    }
}

// ---------------------------------------------------------------------------
extern "C" void kernel_launch(void* const* d_in, const int* in_sizes, int n_in,
                              void* d_out, int out_size) {
    const float* x   = (const float*)d_in[0];
    const float* xTB = (const float*)d_in[1];
    const float* cur = (const float*)d_in[2];
    const int*   ei  = (const int*)  d_in[3];
    const float* att = (const float*)d_in[4];
    const float* W2  = (const float*)d_in[5];
    const float* b2  = (const float*)d_in[6];
    const float* W3  = (const float*)d_in[7];
    const float* b3  = (const float*)d_in[8];
    const float* Wih = (const float*)d_in[9];
    const float* Whh = (const float*)d_in[10];
    const float* bih = (const float*)d_in[11];
    const float* bhh = (const float*)d_in[12];
    const float* W1  = (const float*)d_in[13];
    const float* b1  = (const float*)d_in[14];
    const float* x30 = (const float*)d_in[15];
    float* out = (float*)d_out;

    cudaFuncSetAttribute(gl_main, cudaFuncAttributeMaxDynamicSharedMemorySize,
                         SMEM_BYTES);

    gl_init<<<(Nn + 255) / 256, 256>>>(x, xTB, b3);
    gl_main<<<NBLK, NTHR, SMEM_BYTES>>>(x, cur, ei, att, W2, b2, W3,
                                        Wih, Whh, bih, bhh, W1, b1, x30, out);
}

// round 8
// speedup vs baseline: 1.0282x; 1.0282x over previous
#include <cuda_runtime.h>
#include <cstdint>

#define Nn   8192
#define Ee   262144
#define Tt   2048
#define NMAT 128          // matvec blocks (64 rows / 64 cols each)
#define NBLK (NMAT + 1)   // + 1 LSTM block
#define NTHR 512

// ---- scratch (device globals; no allocation allowed) ----
__device__ float g_v[Nn];        // xTB - x
__device__ float g_x1[Nn];       // edge scatter result
__device__ float g_x2[Nn];       // W3@(W2@v+b2)+b3 (seeded with b3, atomic-accumulated)
__device__ int   g_done;         // matvec blocks finished

// dynamic smem:
//   matvec blocks: s_v[8192] + s_x21[64]
//   LSTM block   : s_cur[2056] + s_h[8+16384] + red[17]
#define SMEM_BYTES ((2056 + 8 + 16384 + 17) * 4)

__device__ __forceinline__ float tanhap(float x) {
    float y;
    asm("tanh.approx.f32 %0, %1;" : "=f"(y) : "f"(x));
    return y;
}

// ---------------------------------------------------------------------------
// K0: init — g_x1 = 0, g_x2 = b3 (atomic accumulation base), v = xTB - x
// ---------------------------------------------------------------------------
__global__ void gl_init(const float* __restrict__ x, const float* __restrict__ xTB,
                        const float* __restrict__ b3) {
    int i = blockIdx.x * blockDim.x + threadIdx.x;
    if (i < Nn) {
        g_v[i]  = xTB[i] - x[i];
        g_x1[i] = 0.f;
        g_x2[i] = b3[i];
    }
    if (i == 0) g_done = 0;
}

// ---------------------------------------------------------------------------
// K1: mega kernel (barrier-free matvec chain + LSTM block)
// ---------------------------------------------------------------------------
__global__ void __launch_bounds__(NTHR, 1)
gl_main(const float* __restrict__ x,   const float* __restrict__ cur,
        const int*   __restrict__ ei,  const float* __restrict__ att,
        const float* __restrict__ W2,  const float* __restrict__ b2,
        const float* __restrict__ W3,
        const float* __restrict__ Wih, const float* __restrict__ Whh,
        const float* __restrict__ bih, const float* __restrict__ bhh,
        const float* __restrict__ W1,  const float* __restrict__ b1,
        const float* __restrict__ x30, float* __restrict__ out) {
    extern __shared__ float smem[];
    const int lane = threadIdx.x & 31;
    const int warp = threadIdx.x >> 5;

    if (blockIdx.x < NMAT) {
        // ================= matvec / scatter block =================
        float4* sv    = (float4*)smem;          // v staged: 8192 floats
        float*  s_x21 = smem + Nn;              // this block's 64 x21 values

        {   // stage v into smem
            const float4* gv = (const float4*)g_v;
            for (int i = threadIdx.x; i < Nn / 4; i += NTHR) sv[i] = gv[i];
        }
        {   // edge scatter
            int tid  = blockIdx.x * NTHR + threadIdx.x;
            int nthr = NMAT * NTHR;
            for (int e = tid; e < Ee; e += nthr) {
                int s = ei[e];
                int d = ei[Ee + e];
                float m = (__ldg(x + s) - __ldg(x + d)) * __ldg(att + e);
                atomicAdd(&g_x1[d], m);
            }
        }
        __syncthreads();

        // ---- mv1: rows [64b, 64b+64), warp-per-row, 16-deep batched loads ----
        const int row0 = blockIdx.x * 64;
        for (int r = warp; r < 64; r += NTHR / 32) {
            int row = row0 + r;
            const float4* wr = (const float4*)(W2 + (size_t)row * Nn) + lane;
            float acc0 = 0.f, acc1 = 0.f;
            #pragma unroll 1
            for (int c = 0; c < 4; ++c) {
                float4 w[16];
                #pragma unroll
                for (int k = 0; k < 16; ++k)
                    w[k] = __ldg(wr + (c * 16 + k) * 32);
                #pragma unroll
                for (int k = 0; k < 16; ++k) {
                    float4 u = sv[lane + (c * 16 + k) * 32];
                    acc0 = fmaf(w[k].x, u.x, acc0);
                    acc1 = fmaf(w[k].y, u.y, acc1);
                    acc0 = fmaf(w[k].z, u.z, acc0);
                    acc1 = fmaf(w[k].w, u.w, acc1);
                }
            }
            float acc = acc0 + acc1;
            #pragma unroll
            for (int o = 16; o; o >>= 1) acc += __shfl_down_sync(0xffffffffu, acc, o);
            if (lane == 0) s_x21[r] = acc + b2[row];
        }
        __syncthreads();

        // ---- mv2: column slice W3[:, 64b:64b+64) @ s_x21, row-per-lane ----
        const float4* sx = (const float4*)s_x21;
        const int c4 = blockIdx.x * 16;
        #pragma unroll 1
        for (int p = 0; p < Nn / NTHR; ++p) {
            int row = p * NTHR + threadIdx.x;
            const float4* wr = (const float4*)(W3 + (size_t)row * Nn) + c4;
            float a0 = 0.f, a1 = 0.f;
            #pragma unroll
            for (int k = 0; k < 16; ++k) {
                float4 w = __ldg(wr + k);
                float4 u = sx[k];
                a0 = fmaf(w.x, u.x, a0);
                a1 = fmaf(w.y, u.y, a1);
                a0 = fmaf(w.z, u.z, a0);
                a1 = fmaf(w.w, u.w, a1);
            }
            atomicAdd(&g_x2[row], a0 + a1);
        }

        __syncthreads();
        if (threadIdx.x == 0) {
            __threadfence();
            atomicAdd(&g_done, 1);
        }
    } else {
        // ================= LSTM block =================
        float* s_cur = smem;                        // [2056] (padded for prefetch)
        float* s_h   = smem + 2056;                 // [8 + 16384]: slot t holds h(t-1)
        float* s_red = smem + 2056 + 8 + 16384;     // [16]
        float* s_x3  = s_red + 16;

        for (int i = threadIdx.x; i < Tt; i += NTHR) s_cur[i] = cur[i];
        if (threadIdx.x < 8) {
            s_cur[Tt + threadIdx.x] = 0.f;
            s_h[threadIdx.x] = 0.f;                 // h(-1) = 0
        }
        __syncthreads();

        if (warp == 0) {
            // gate-per-lane: lane = gt*8 + u
            // sigmoid gates (gt 0,1,3) via 0.5*tanh(z/2)+0.5; gate 2 tanh
            const int u  = lane & 7;
            const int gt = lane >> 3;
            const bool sig = (gt != 2);
            const bool is_o = (gt == 3);            // o-lanes produce & store h
            const float wscale = sig ? 0.5f : 1.0f;
            const float sca = sig ? 0.5f : 1.0f;
            const float scb = sig ? 0.5f : 0.0f;

            float w0 = wscale * Whh[lane * 8 + 0];
            float w1 = wscale * Whh[lane * 8 + 1];
            float w2 = wscale * Whh[lane * 8 + 2];
            float w3 = wscale * Whh[lane * 8 + 3];
            float w4 = wscale * Whh[lane * 8 + 4];
            float w5 = wscale * Whh[lane * 8 + 5];
            float w6 = wscale * Whh[lane * 8 + 6];
            float w7 = wscale * Whh[lane * 8 + 7];
            float a  = wscale * Wih[lane];
            float bb = wscale * (bih[lane] + bhh[lane]);

            float c = 0.f;
            float xt = s_cur[0];
            uint32_t hrd = (uint32_t)__cvta_generic_to_shared(s_h);          // h(t-1) @ +t*32B
            float* shp = s_h + 8 + u;                                        // h(t) store

            #pragma unroll 8
            for (int t = 0; t < Tt; t++) {
                float4 hlo, hhi;
                asm volatile("ld.shared.v4.f32 {%0,%1,%2,%3}, [%4];"
                             : "=f"(hlo.x), "=f"(hlo.y), "=f"(hlo.z), "=f"(hlo.w)
                             : "r"(hrd + t * 32));
                asm volatile("ld.shared.v4.f32 {%0,%1,%2,%3}, [%4];"
                             : "=f"(hhi.x), "=f"(hhi.y), "=f"(hhi.z), "=f"(hhi.w)
                             : "r"(hrd + t * 32 + 16));

                float pre = fmaf(a, xt, bb);
                float xn  = s_cur[t + 1];           // prefetch (off-chain)

                // 4-accumulator tree dot (depth 2 FMA + 2 ADD)
                float a0 = fmaf(w0, hlo.x, pre);
                float a1 = w2 * hlo.z;
                float a2 = w4 * hhi.x;
                float a3 = w6 * hhi.z;
                a0 = fmaf(w1, hlo.y, a0);
                a1 = fmaf(w3, hlo.w, a1);
                a2 = fmaf(w5, hhi.y, a2);
                a3 = fmaf(w7, hhi.w, a3);
                float z = (a0 + a1) + (a2 + a3);

                float v = fmaf(tanhap(z), sca, scb);   // gate value (gt,u)

                // gather i, f, g only (o is local to lanes 24-31)
                float si = __shfl_sync(0xffffffffu, v, u);
                float sf = __shfl_sync(0xffffffffu, v, 8 + u);
                float tg = __shfl_sync(0xffffffffu, v, 16 + u);

                c = fmaf(sf, c, si * tg);
                float h = v * tanhap(c);            // valid h only in o-lanes

                if (is_o) shp[t * 8] = h;           // hoisted pred -> @P STS
                xt = xn;
            }
        }
        __syncthreads();   // s_h visible block-wide

        // x3 scalar = W1 · hs_flat + b1
        const float* hist = s_h + 8;
        float part = 0.f;
        for (int k = threadIdx.x; k < Tt * 8; k += NTHR)
            part = fmaf(__ldg(W1 + k), hist[k], part);
        #pragma unroll
        for (int o = 16; o; o >>= 1) part += __shfl_down_sync(0xffffffffu, part, o);
        if (lane == 0) s_red[warp] = part;
        __syncthreads();
        if (threadIdx.x == 0) {
            float s = 0.f;
            #pragma unroll
            for (int w = 0; w < NTHR / 32; w++) s += s_red[w];
            *s_x3 = s + b1[0];
            while (atomicAdd(&g_done, 0) < NMAT) {}  // wait for matvec blocks
            __threadfence();
        }
        __syncthreads();

        float x3 = *s_x3;
        for (int i = threadIdx.x; i < Nn; i += NTHR)
            out[i] = x[i] + g_x1[i] + g_x2[i] + x3 * x30[i];
    }
}

// ---------------------------------------------------------------------------
extern "C" void kernel_launch(void* const* d_in, const int* in_sizes, int n_in,
                              void* d_out, int out_size) {
    const float* x   = (const float*)d_in[0];
    const float* xTB = (const float*)d_in[1];
    const float* cur = (const float*)d_in[2];
    const int*   ei  = (const int*)  d_in[3];
    const float* att = (const float*)d_in[4];
    const float* W2  = (const float*)d_in[5];
    const float* b2  = (const float*)d_in[6];
    const float* W3  = (const float*)d_in[7];
    const float* b3  = (const float*)d_in[8];
    const float* Wih = (const float*)d_in[9];
    const float* Whh = (const float*)d_in[10];
    const float* bih = (const float*)d_in[11];
    const float* bhh = (const float*)d_in[12];
    const float* W1  = (const float*)d_in[13];
    const float* b1  = (const float*)d_in[14];
    const float* x30 = (const float*)d_in[15];
    float* out = (float*)d_out;

    cudaFuncSetAttribute(gl_main, cudaFuncAttributeMaxDynamicSharedMemorySize,
                         SMEM_BYTES);

    gl_init<<<(Nn + 255) / 256, 256>>>(x, xTB, b3);
    gl_main<<<NBLK, NTHR, SMEM_BYTES>>>(x, cur, ei, att, W2, b2, W3,
                                        Wih, Whh, bih, bhh, W1, b1, x30, out);
}